// round 3
// baseline (speedup 1.0000x reference)
#include <cuda_runtime.h>

#define TT   1024
#define BB   16
#define HH   512
#define G4H  2048
#define NBLK 128
#define NTHR 256

// ------------- device-global scratch (no runtime allocation allowed) -------------
__device__ float g_gx[(size_t)BB * TT * G4H];   // 134 MB: gx[b][t][gatecol]
__device__ float g_y [(size_t)BB * TT * HH];    // 33.5 MB: layer-0 hidden outputs
__device__ float g_hA[BB * HH];                 // h ping buffer, layout [b][j]
__device__ float g_hB[BB * HH];                 // h pong buffer
__device__ unsigned g_bar_count = 0;
__device__ unsigned g_bar_epoch = 0;

// ------------- packed f32x2 FMA (FFMA2 only reachable via PTX) -------------
__device__ __forceinline__ void fma2(unsigned long long& d,
                                     unsigned long long a,
                                     unsigned long long b)
{
    asm("fma.rn.f32x2 %0, %1, %2, %0;" : "+l"(d) : "l"(a), "l"(b));
}

// =====================================================================
// GEMM: g_gx[m][n] = sum_k X[m][k] * W[n][k] + bias[n]
// M=16384 (b*T+t), N=2048 (gate cols), K=512. Both operands K-contiguous.
// BM=128, BN=128, BK=16, 256 threads, 8x8 per-thread tile, f32x2 over N.
// =====================================================================
__global__ void __launch_bounds__(256, 2) gemm_xw(const float* __restrict__ Xext,
                                                  const float* __restrict__ W,
                                                  const float* __restrict__ bias,
                                                  int use_y)
{
    const float* X = use_y ? g_y : Xext;

    __shared__ float2 As[16][130];   // A value duplicated into a pair; padded row
    __shared__ float  Bs[16][132];   // transposed B tile; padded row

    const int m0  = blockIdx.y * 128;
    const int n0  = blockIdx.x * 128;
    const int tid = threadIdx.x;
    const int tm  = tid >> 4;        // 0..15 -> rows tm*8..tm*8+7
    const int tn  = tid & 15;        // 0..15 -> cols tn*8..tn*8+7
    const int lr  = tid >> 2;        // 0..63 loader row
    const int lk  = (tid & 3) * 4;   // 0,4,8,12 loader k

    unsigned long long acc[8][4];
#pragma unroll
    for (int i = 0; i < 8; i++)
#pragma unroll
        for (int j = 0; j < 4; j++) acc[i][j] = 0ULL;

    for (int k0 = 0; k0 < 512; k0 += 16) {
        float4 av0 = *(const float4*)&X[(size_t)(m0 + lr)      * 512 + k0 + lk];
        float4 av1 = *(const float4*)&X[(size_t)(m0 + lr + 64) * 512 + k0 + lk];
        float4 bv0 = *(const float4*)&W[(size_t)(n0 + lr)      * 512 + k0 + lk];
        float4 bv1 = *(const float4*)&W[(size_t)(n0 + lr + 64) * 512 + k0 + lk];

        __syncthreads();   // previous tile's compute done
        As[lk + 0][lr]      = make_float2(av0.x, av0.x);
        As[lk + 1][lr]      = make_float2(av0.y, av0.y);
        As[lk + 2][lr]      = make_float2(av0.z, av0.z);
        As[lk + 3][lr]      = make_float2(av0.w, av0.w);
        As[lk + 0][lr + 64] = make_float2(av1.x, av1.x);
        As[lk + 1][lr + 64] = make_float2(av1.y, av1.y);
        As[lk + 2][lr + 64] = make_float2(av1.z, av1.z);
        As[lk + 3][lr + 64] = make_float2(av1.w, av1.w);
        Bs[lk + 0][lr]      = bv0.x;
        Bs[lk + 1][lr]      = bv0.y;
        Bs[lk + 2][lr]      = bv0.z;
        Bs[lk + 3][lr]      = bv0.w;
        Bs[lk + 0][lr + 64] = bv1.x;
        Bs[lk + 1][lr + 64] = bv1.y;
        Bs[lk + 2][lr + 64] = bv1.z;
        Bs[lk + 3][lr + 64] = bv1.w;
        __syncthreads();

#pragma unroll
        for (int k = 0; k < 16; k++) {
            unsigned long long a[8], b[4];
            ulonglong2 q;
            q = *(const ulonglong2*)&As[k][tm * 8 + 0]; a[0] = q.x; a[1] = q.y;
            q = *(const ulonglong2*)&As[k][tm * 8 + 2]; a[2] = q.x; a[3] = q.y;
            q = *(const ulonglong2*)&As[k][tm * 8 + 4]; a[4] = q.x; a[5] = q.y;
            q = *(const ulonglong2*)&As[k][tm * 8 + 6]; a[6] = q.x; a[7] = q.y;
            q = *(const ulonglong2*)&Bs[k][tn * 8 + 0]; b[0] = q.x; b[1] = q.y;
            q = *(const ulonglong2*)&Bs[k][tn * 8 + 4]; b[2] = q.x; b[3] = q.y;
#pragma unroll
            for (int i = 0; i < 8; i++)
#pragma unroll
                for (int j = 0; j < 4; j++)
                    fma2(acc[i][j], a[i], b[j]);
        }
    }

    float bl[8];
#pragma unroll
    for (int j = 0; j < 8; j++) bl[j] = bias[n0 + tn * 8 + j];

#pragma unroll
    for (int i = 0; i < 8; i++) {
        int row = m0 + tm * 8 + i;
        union { unsigned long long u; float2 f; } v0, v1, v2, v3;
        v0.u = acc[i][0]; v1.u = acc[i][1]; v2.u = acc[i][2]; v3.u = acc[i][3];
        float4 o0 = make_float4(v0.f.x + bl[0], v0.f.y + bl[1],
                                v1.f.x + bl[2], v1.f.y + bl[3]);
        float4 o1 = make_float4(v2.f.x + bl[4], v2.f.y + bl[5],
                                v3.f.x + bl[6], v3.f.y + bl[7]);
        *(float4*)&g_gx[(size_t)row * G4H + n0 + tn * 8]     = o0;
        *(float4*)&g_gx[(size_t)row * G4H + n0 + tn * 8 + 4] = o1;
    }
}

// =====================================================================
// Grid barrier for 128 co-resident blocks (1 wave on 148 SMs).
// Every thread fences its own writes; thread 0 arrives and spins on epoch.
// =====================================================================
__device__ __forceinline__ void grid_barrier(unsigned target)
{
    __threadfence();
    __syncthreads();
    if (threadIdx.x == 0) {
        unsigned t = atomicAdd(&g_bar_count, 1);
        if (t == NBLK - 1) {
            atomicExch(&g_bar_count, 0);
            __threadfence();
            atomicAdd(&g_bar_epoch, 1);
        } else {
            while ((int)(*(volatile unsigned*)&g_bar_epoch - target) < 0)
                __nanosleep(32);
        }
    }
    __syncthreads();
}

// =====================================================================
// Persistent recurrent kernel. 128 blocks x 256 threads.
// Block owns 4 hidden units j0..j0+3 => 16 gate columns (4 gates x 4 j).
// Thread (colIdx = tid>>4, b = tid&15) computes one gate pre-activation.
// w_hh slice (16x512 = 32KB) and c state stay in shared the whole layer.
// h ping-pongs via g_hA/g_hB (read L1-bypassed with __ldcg).
// =====================================================================
__global__ void __launch_bounds__(256, 1) lstm_rec(
    const float* __restrict__ w_hh, const float* __restrict__ b_hh,
    const float* __restrict__ h0l,  const float* __restrict__ c0l,
    float* __restrict__ hfin, int write_y)
{
    __shared__ float w_sh[16 * 512];   // w_sh[l*512 + k]
    __shared__ float h_ch[16 * 132];   // staged h chunk, h_ch[b*132 + kk]
    __shared__ float gatesS[16 * 17];  // activated gates, gatesS[l*17 + b]
    __shared__ float c_sh[64];         // c_sh[j*16 + b]

    const int tid    = threadIdx.x;
    const int blk    = blockIdx.x;
    const int j0     = blk * 4;
    const int colIdx = tid >> 4;          // 0..15
    const int b      = tid & 15;
    const int gate   = colIdx >> 2;       // 0=i 1=f 2=g 3=o
    const int jj     = colIdx & 3;
    const int gcol   = gate * 512 + j0 + jj;

    // ---- one-time init ----
    for (int i = tid; i < 16 * 512; i += 256) {
        int l = i >> 9, k = i & 511;
        int gc = (l >> 2) * 512 + j0 + (l & 3);
        w_sh[i] = w_hh[gc * 512 + k];
    }
    if (tid < 64) {
        int bb = tid & 15, j = tid >> 4;
        c_sh[j * 16 + bb] = c0l[bb * 512 + j0 + j];
        g_hA[bb * 512 + j0 + j] = h0l[bb * 512 + j0 + j];
    }
    const float bhh = b_hh[gcol];

    unsigned base = 0;
    if (tid == 0) base = *(volatile unsigned*)&g_bar_epoch;
    grid_barrier(base + 1);   // all blocks' h/w init visible

    for (int t = 0; t < TT; t++) {
        const float* hsrc = (t & 1) ? g_hB : g_hA;
        float*       hdst = (t & 1) ? g_hA : g_hB;

        float gxv = g_gx[(size_t)(b * TT + t) * G4H + gcol];  // prefetch early

        float a0 = 0.f, a1 = 0.f, a2 = 0.f, a3 = 0.f;
#pragma unroll 1
        for (int c4 = 0; c4 < 4; c4++) {
            const int k0 = c4 << 7;
            // stage 16x128 h chunk (L1 bypass — other SMs rewrote it)
#pragma unroll
            for (int rep = 0; rep < 2; rep++) {
                int vv  = tid + rep * 256;          // 0..511
                int bb  = vv >> 5;
                int kk4 = (vv & 31) << 2;
                *(float4*)&h_ch[bb * 132 + kk4] =
                    __ldcg((const float4*)&hsrc[bb * 512 + k0 + kk4]);
            }
            __syncthreads();
            const float* wr = &w_sh[colIdx * 512 + k0];
            const float* hr = &h_ch[b * 132];
#pragma unroll
            for (int kk = 0; kk < 128; kk += 4) {
                float4 w4 = *(const float4*)&wr[kk];
                float4 h4 = *(const float4*)&hr[kk];
                a0 += w4.x * h4.x;
                a1 += w4.y * h4.y;
                a2 += w4.z * h4.z;
                a3 += w4.w * h4.w;
            }
            __syncthreads();
        }

        float val = (a0 + a2) + (a1 + a3) + gxv + bhh;
        float act = (gate == 2) ? tanhf(val) : 1.f / (1.f + __expf(-val));
        gatesS[colIdx * 17 + b] = act;
        __syncthreads();

        if (tid < 64) {
            int bb = tid & 15, j = tid >> 4;
            float iv = gatesS[(0  + j) * 17 + bb];
            float fv = gatesS[(4  + j) * 17 + bb];
            float gv = gatesS[(8  + j) * 17 + bb];
            float ov = gatesS[(12 + j) * 17 + bb];
            float c  = fv * c_sh[j * 16 + bb] + iv * gv;
            c_sh[j * 16 + bb] = c;
            float h = ov * tanhf(c);
            hdst[bb * 512 + j0 + j] = h;
            if (write_y)     g_y[(size_t)(bb * TT + t) * 512 + j0 + j] = h;
            if (t == TT - 1) hfin[bb * 512 + j0 + j] = h;
        }
        grid_barrier(base + 2 + t);
    }
}

// =====================================================================
extern "C" void kernel_launch(void* const* d_in, const int* in_sizes, int n_in,
                              void* d_out, int out_size)
{
    const float* x      = (const float*)d_in[0];
    const float* h0     = (const float*)d_in[1];   // (2, B, H)
    const float* c0     = (const float*)d_in[2];   // (2, B, H)
    const float* w_ih_0 = (const float*)d_in[3];
    const float* w_hh_0 = (const float*)d_in[4];
    const float* b_ih_0 = (const float*)d_in[5];
    const float* b_hh_0 = (const float*)d_in[6];
    const float* w_ih_1 = (const float*)d_in[7];
    const float* w_hh_1 = (const float*)d_in[8];
    const float* b_ih_1 = (const float*)d_in[9];
    const float* b_hh_1 = (const float*)d_in[10];
    float* out = (float*)d_out;                    // (2, B, H)

    dim3 ggrid(16, 128);   // N/128, M/128
    gemm_xw<<<ggrid, 256>>>(x, w_ih_0, b_ih_0, 0);
    lstm_rec<<<NBLK, NTHR>>>(w_hh_0, b_hh_0, h0, c0, out, 1);
    gemm_xw<<<ggrid, 256>>>(x, w_ih_1, b_ih_1, 1);
    lstm_rec<<<NBLK, NTHR>>>(w_hh_1, b_hh_1, h0 + BB * HH, c0 + BB * HH,
                             out + BB * HH, 0);
}

// round 6
// speedup vs baseline: 2.3550x; 2.3550x over previous
#include <cuda_runtime.h>

#define TT   1024
#define BB   16
#define HH   512
#define G4H  2048
#define NBLK 128
#define NTHR 256

typedef unsigned long long ull;

// ------------- device-global scratch (no runtime allocation allowed) -------------
__device__ float g_gx[(size_t)BB * TT * G4H];   // 134 MB: gx[b][t][gatecol]
__device__ float g_y [(size_t)BB * TT * HH];    // 33.5 MB: layer-0 hidden outputs
__device__ __align__(16) ull g_h2A[8 * 512];    // h ping, packed pairs: [bp][j] = (h[2bp][j], h[2bp+1][j])
__device__ __align__(16) ull g_h2B[8 * 512];    // h pong
__device__ unsigned g_bar_count = 0;
__device__ unsigned g_bar_epoch = 0;

// ------------- packed f32x2 ops (only reachable via PTX) -------------
__device__ __forceinline__ void fma2(ull& d, ull a, ull b)
{
    asm("fma.rn.f32x2 %0, %1, %2, %0;" : "+l"(d) : "l"(a), "l"(b));
}
__device__ __forceinline__ ull pack2(float a, float b)
{
    ull r; asm("mov.b64 %0, {%1, %2};" : "=l"(r) : "f"(a), "f"(b)); return r;
}
__device__ __forceinline__ float2 unpack2(ull v)
{
    float2 r; asm("mov.b64 {%0, %1}, %2;" : "=f"(r.x), "=f"(r.y) : "l"(v)); return r;
}
__device__ __forceinline__ void ldcg_v2u64(ull& a, ull& b, const ull* p)
{
    asm volatile("ld.global.cg.v2.u64 {%0, %1}, [%2];" : "=l"(a), "=l"(b) : "l"(p));
}

// =====================================================================
// GEMM: g_gx[m][n] = sum_k X[m][k] * W[n][k] + bias[n]
// M=16384 (b*T+t), N=2048 (gate cols), K=512. Both operands K-contiguous.
// BM=128, BN=128, BK=16, 256 threads, 8x8 per-thread tile, f32x2 over N.
// =====================================================================
__global__ void __launch_bounds__(256, 2) gemm_xw(const float* __restrict__ Xext,
                                                  const float* __restrict__ W,
                                                  const float* __restrict__ bias,
                                                  int use_y)
{
    const float* X = use_y ? g_y : Xext;

    __shared__ float2 As[16][130];   // A value duplicated into a pair; padded row
    __shared__ float  Bs[16][132];   // transposed B tile; padded row

    const int m0  = blockIdx.y * 128;
    const int n0  = blockIdx.x * 128;
    const int tid = threadIdx.x;
    const int tm  = tid >> 4;        // 0..15 -> rows tm*8..tm*8+7
    const int tn  = tid & 15;        // 0..15 -> cols tn*8..tn*8+7
    const int lr  = tid >> 2;        // 0..63 loader row
    const int lk  = (tid & 3) * 4;   // 0,4,8,12 loader k

    ull acc[8][4];
#pragma unroll
    for (int i = 0; i < 8; i++)
#pragma unroll
        for (int j = 0; j < 4; j++) acc[i][j] = 0ULL;

    for (int k0 = 0; k0 < 512; k0 += 16) {
        float4 av0 = *(const float4*)&X[(size_t)(m0 + lr)      * 512 + k0 + lk];
        float4 av1 = *(const float4*)&X[(size_t)(m0 + lr + 64) * 512 + k0 + lk];
        float4 bv0 = *(const float4*)&W[(size_t)(n0 + lr)      * 512 + k0 + lk];
        float4 bv1 = *(const float4*)&W[(size_t)(n0 + lr + 64) * 512 + k0 + lk];

        __syncthreads();   // previous tile's compute done
        As[lk + 0][lr]      = make_float2(av0.x, av0.x);
        As[lk + 1][lr]      = make_float2(av0.y, av0.y);
        As[lk + 2][lr]      = make_float2(av0.z, av0.z);
        As[lk + 3][lr]      = make_float2(av0.w, av0.w);
        As[lk + 0][lr + 64] = make_float2(av1.x, av1.x);
        As[lk + 1][lr + 64] = make_float2(av1.y, av1.y);
        As[lk + 2][lr + 64] = make_float2(av1.z, av1.z);
        As[lk + 3][lr + 64] = make_float2(av1.w, av1.w);
        Bs[lk + 0][lr]      = bv0.x;
        Bs[lk + 1][lr]      = bv0.y;
        Bs[lk + 2][lr]      = bv0.z;
        Bs[lk + 3][lr]      = bv0.w;
        Bs[lk + 0][lr + 64] = bv1.x;
        Bs[lk + 1][lr + 64] = bv1.y;
        Bs[lk + 2][lr + 64] = bv1.z;
        Bs[lk + 3][lr + 64] = bv1.w;
        __syncthreads();

#pragma unroll
        for (int k = 0; k < 16; k++) {
            ull a[8], b[4];
            ulonglong2 q;
            q = *(const ulonglong2*)&As[k][tm * 8 + 0]; a[0] = q.x; a[1] = q.y;
            q = *(const ulonglong2*)&As[k][tm * 8 + 2]; a[2] = q.x; a[3] = q.y;
            q = *(const ulonglong2*)&As[k][tm * 8 + 4]; a[4] = q.x; a[5] = q.y;
            q = *(const ulonglong2*)&As[k][tm * 8 + 6]; a[6] = q.x; a[7] = q.y;
            q = *(const ulonglong2*)&Bs[k][tn * 8 + 0]; b[0] = q.x; b[1] = q.y;
            q = *(const ulonglong2*)&Bs[k][tn * 8 + 4]; b[2] = q.x; b[3] = q.y;
#pragma unroll
            for (int i = 0; i < 8; i++)
#pragma unroll
                for (int j = 0; j < 4; j++)
                    fma2(acc[i][j], a[i], b[j]);
        }
    }

    float bl[8];
#pragma unroll
    for (int j = 0; j < 8; j++) bl[j] = bias[n0 + tn * 8 + j];

#pragma unroll
    for (int i = 0; i < 8; i++) {
        int row = m0 + tm * 8 + i;
        float2 v0 = unpack2(acc[i][0]), v1 = unpack2(acc[i][1]);
        float2 v2 = unpack2(acc[i][2]), v3 = unpack2(acc[i][3]);
        float4 o0 = make_float4(v0.x + bl[0], v0.y + bl[1], v1.x + bl[2], v1.y + bl[3]);
        float4 o1 = make_float4(v2.x + bl[4], v2.y + bl[5], v3.x + bl[6], v3.y + bl[7]);
        *(float4*)&g_gx[(size_t)row * G4H + n0 + tn * 8]     = o0;
        *(float4*)&g_gx[(size_t)row * G4H + n0 + tn * 8 + 4] = o1;
    }
}

// =====================================================================
// Grid barrier for 128 co-resident blocks (1 wave, <= #SMs).
// =====================================================================
__device__ __forceinline__ void grid_barrier(unsigned target)
{
    __threadfence();
    __syncthreads();
    if (threadIdx.x == 0) {
        unsigned t = atomicAdd(&g_bar_count, 1);
        if (t == NBLK - 1) {
            atomicExch(&g_bar_count, 0);
            __threadfence();
            atomicAdd(&g_bar_epoch, 1);
        } else {
            while ((int)(*(volatile unsigned*)&g_bar_epoch - target) < 0) { }
        }
    }
    __syncthreads();
}

// =====================================================================
// Persistent recurrent kernel. 128 blocks x 256 threads.
// Block owns 4 hidden units j0..j0+3 -> 16 gate cols (4 gates x 4 j).
// Thread (l = tid&15, ksub = tid>>4):
//   - w_hh[gcol(l)][k] for k in {i*32 + ksub*2, i*32 + ksub*2 + 1 : i=0..15}
//     lives in 32 f32x2-duplicated REGISTERS for the whole kernel.
//   - per step: 8 batch-pair accumulators via FFMA2 against h pairs
//     broadcast from smem (two adjacent 16B chunks per warp -> conflict-free).
// Reduction over ksub: shfl_xor(16) + 8-way smem tree.
// h ping-pongs through global pair buffers (L1 bypassed with ld.cg).
// =====================================================================
__global__ void __launch_bounds__(256, 1) lstm_rec(
    const float* __restrict__ w_hh, const float* __restrict__ b_hh,
    const float* __restrict__ h0l,  const float* __restrict__ c0l,
    float* __restrict__ hfin, int write_y)
{
    __shared__ __align__(16) ull hp_sh[8 * 512];    // h pairs, [bp][k], 32 KB
    __shared__ __align__(16) ull red[8 * 128];      // partials, [warp][l*8+bp], 8 KB
    __shared__ __align__(16) ull gact[128];         // activated gates, [l*8+bp], 1 KB
    __shared__ __align__(16) ull c2_sh[32];         // cell pairs, [j*8+bp]

    const int tid  = threadIdx.x;
    const int blk  = blockIdx.x;
    const int j0   = blk * 4;
    const int l    = tid & 15;           // gate column within block
    const int ksub = tid >> 4;           // 0..15 k-split
    const int wid  = tid >> 5;           // warp id = ksub>>1
    const int gcol = (l >> 2) * 512 + j0 + (l & 3);

    // reducer-role constants (threads 0..127): l2 = tid>>3, bp2 = tid&7
    const int l2    = tid >> 3;
    const int bp2   = tid & 7;
    const int gc2   = (l2 >> 2) * 512 + j0 + (l2 & 3);
    const int gate2 = l2 >> 2;
    float bhh2 = 0.f;
    if (tid < 128) bhh2 = b_hh[gc2];

    // ---- load w slice into registers, f32x2-duplicated ----
    // k = i*32 + ksub*2 (+1): i=0..15, ksub=0..15 -> covers k in [0,512)
    ull wd[32];
#pragma unroll
    for (int i = 0; i < 16; i++) {
        float2 wv = *(const float2*)&w_hh[(size_t)gcol * 512 + i * 32 + ksub * 2];
        wd[2 * i]     = pack2(wv.x, wv.x);
        wd[2 * i + 1] = pack2(wv.y, wv.y);
    }

    // ---- init c pairs + this block's h0 slice (packed pairs) ----
    if (tid < 32) {
        int j = tid >> 3, bp = tid & 7;
        c2_sh[j * 8 + bp] = pack2(c0l[(2 * bp) * 512 + j0 + j],
                                  c0l[(2 * bp + 1) * 512 + j0 + j]);
        g_h2A[bp * 512 + j0 + j] = pack2(h0l[(2 * bp) * 512 + j0 + j],
                                         h0l[(2 * bp + 1) * 512 + j0 + j]);
    }

    unsigned base = 0;
    if (tid == 0) base = *(volatile unsigned*)&g_bar_epoch;
    grid_barrier(base + 1);   // all blocks' h init visible

    for (int t = 0; t < TT; t++) {
        const ull* hsrc = (t & 1) ? g_h2B : g_h2A;
        ull*       hdst = (t & 1) ? g_h2A : g_h2B;

        // prefetch gx for reducer role (independent of everything below)
        float gxa = 0.f, gxb = 0.f;
        if (tid < 128) {
            gxa = g_gx[((size_t)(2 * bp2) * TT + t) * G4H + gc2];
            gxb = g_gx[((size_t)(2 * bp2 + 1) * TT + t) * G4H + gc2];
        }

        // ---- stage h pairs: 32 KB global -> smem (L1 bypass, batched MLP) ----
        {
            ull ta[8], tb[8];
#pragma unroll
            for (int r = 0; r < 8; r++)
                ldcg_v2u64(ta[r], tb[r], hsrc + 2 * (tid + r * 256));
#pragma unroll
            for (int r = 0; r < 8; r++) {
                hp_sh[2 * (tid + r * 256)]     = ta[r];
                hp_sh[2 * (tid + r * 256) + 1] = tb[r];
            }
        }
        __syncthreads();

        // ---- MMA: 8 batch-pair accumulators, w in regs, h broadcast from smem ----
        ull acc[8];
#pragma unroll
        for (int bp = 0; bp < 8; bp++) acc[bp] = 0ULL;
#pragma unroll
        for (int i = 0; i < 16; i++) {
            const int off = i * 32 + ksub * 2;
#pragma unroll
            for (int bp = 0; bp < 8; bp++) {
                ulonglong2 q = *(const ulonglong2*)&hp_sh[bp * 512 + off];
                fma2(acc[bp], wd[2 * i],     q.x);
                fma2(acc[bp], wd[2 * i + 1], q.y);
            }
        }

        // ---- reduce over ksub: shfl pair-combine, then 8-way smem tree ----
#pragma unroll
        for (int bp = 0; bp < 8; bp++) {
            ull other = __shfl_xor_sync(0xffffffffu, acc[bp], 16);
            float2 a = unpack2(acc[bp]), o = unpack2(other);
            acc[bp] = pack2(a.x + o.x, a.y + o.y);
        }
        if ((tid & 31) < 16) {
            ulonglong2* dst = (ulonglong2*)&red[wid * 128 + l * 8];
            dst[0] = make_ulonglong2(acc[0], acc[1]);
            dst[1] = make_ulonglong2(acc[2], acc[3]);
            dst[2] = make_ulonglong2(acc[4], acc[5]);
            dst[3] = make_ulonglong2(acc[6], acc[7]);
        }
        __syncthreads();

        if (tid < 128) {
            float sx = 0.f, sy = 0.f;
#pragma unroll
            for (int w = 0; w < 8; w++) {
                float2 p = unpack2(red[w * 128 + tid]);
                sx += p.x; sy += p.y;
            }
            float vx = sx + gxa + bhh2;
            float vy = sy + gxb + bhh2;
            float ax, ay;
            if (gate2 == 2) { ax = tanhf(vx); ay = tanhf(vy); }
            else            { ax = 1.f / (1.f + __expf(-vx));
                              ay = 1.f / (1.f + __expf(-vy)); }
            gact[tid] = pack2(ax, ay);
        }
        __syncthreads();

        // ---- cell/hidden update: 32 threads, each a (j, batch-pair) ----
        if (tid < 32) {
            int j = tid >> 3, bp = tid & 7;
            float2 iv = unpack2(gact[(0  + j) * 8 + bp]);
            float2 fv = unpack2(gact[(4  + j) * 8 + bp]);
            float2 gv = unpack2(gact[(8  + j) * 8 + bp]);
            float2 ov = unpack2(gact[(12 + j) * 8 + bp]);
            float2 c  = unpack2(c2_sh[j * 8 + bp]);
            c.x = fv.x * c.x + iv.x * gv.x;
            c.y = fv.y * c.y + iv.y * gv.y;
            c2_sh[j * 8 + bp] = pack2(c.x, c.y);
            float hx = ov.x * tanhf(c.x);
            float hy = ov.y * tanhf(c.y);
            hdst[bp * 512 + j0 + j] = pack2(hx, hy);
            if (write_y) {
                g_y[((size_t)(2 * bp) * TT + t) * HH + j0 + j]     = hx;
                g_y[((size_t)(2 * bp + 1) * TT + t) * HH + j0 + j] = hy;
            }
            if (t == TT - 1) {
                hfin[(2 * bp) * HH + j0 + j]     = hx;
                hfin[(2 * bp + 1) * HH + j0 + j] = hy;
            }
        }
        grid_barrier(base + 2 + t);
    }
}

// =====================================================================
extern "C" void kernel_launch(void* const* d_in, const int* in_sizes, int n_in,
                              void* d_out, int out_size)
{
    const float* x      = (const float*)d_in[0];
    const float* h0     = (const float*)d_in[1];   // (2, B, H)
    const float* c0     = (const float*)d_in[2];   // (2, B, H)
    const float* w_ih_0 = (const float*)d_in[3];
    const float* w_hh_0 = (const float*)d_in[4];
    const float* b_ih_0 = (const float*)d_in[5];
    const float* b_hh_0 = (const float*)d_in[6];
    const float* w_ih_1 = (const float*)d_in[7];
    const float* w_hh_1 = (const float*)d_in[8];
    const float* b_ih_1 = (const float*)d_in[9];
    const float* b_hh_1 = (const float*)d_in[10];
    float* out = (float*)d_out;                    // (2, B, H)

    dim3 ggrid(16, 128);   // N/128, M/128
    gemm_xw<<<ggrid, 256>>>(x, w_ih_0, b_ih_0, 0);
    lstm_rec<<<NBLK, NTHR>>>(w_hh_0, b_hh_0, h0, c0, out, 1);
    gemm_xw<<<ggrid, 256>>>(x, w_ih_1, b_ih_1, 1);
    lstm_rec<<<NBLK, NTHR>>>(w_hh_1, b_hh_1, h0 + BB * HH, c0 + BB * HH,
                             out + BB * HH, 0);
}